// round 8
// baseline (speedup 1.0000x reference)
#include <cuda_runtime.h>
#include <cuda_bf16.h>
#include <math.h>
#include <stdint.h>

#define TT   512
#define BB   64
#define HH   512
#define LL   2
#define NBLK 128          // recurrence grid (1 CTA/SM, all co-resident)

typedef unsigned long long ull;

// ---------------- scratch (__device__ globals; allocation-free) ----------------
__device__ float g_gx[3][TT * BB * HH];     // gate-x planes (r,z,n) for current layer
__device__ float g_ht[2][HH * BB];          // double-buffered hidden state, k-major [k][b]
__device__ unsigned int g_flags[NBLK * 32]; // per-CTA barrier flags, 128B stride

// ---------------- packed fp32x2 helpers (Blackwell) -----------------------------
__device__ __forceinline__ ull pk2(float x) {
    ull r; asm("mov.b64 %0, {%1, %1};" : "=l"(r) : "f"(x)); return r;
}
__device__ __forceinline__ void fma2(ull& acc, ull a, ull b) {
    asm("fma.rn.f32x2 %0, %1, %2, %0;" : "+l"(acc) : "l"(a), "l"(b));
}

// tf32 round-to-nearest of an fp32 (bits usable by mma.tf32)
__device__ __forceinline__ float tf32r(float x) {
    uint32_t y;
    asm("cvt.rna.tf32.f32 %0, %1;" : "=r"(y) : "f"(x));
    return __uint_as_float(y);
}

__device__ __forceinline__ void mma_tf32(float c[4], const uint32_t a[4],
                                         const uint32_t b[2]) {
    asm volatile(
        "mma.sync.aligned.m16n8k8.row.col.f32.tf32.tf32.f32 "
        "{%0,%1,%2,%3}, {%4,%5,%6,%7}, {%8,%9}, {%0,%1,%2,%3};"
        : "+f"(c[0]), "+f"(c[1]), "+f"(c[2]), "+f"(c[3])
        : "r"(a[0]), "r"(a[1]), "r"(a[2]), "r"(a[3]), "r"(b[0]), "r"(b[1]));
}

// ---------------- h0 transpose + barrier-flag reset ------------------------------
__global__ __launch_bounds__(256) void transpose_h0(const float* __restrict__ h0) {
    const int i = blockIdx.x * 256 + threadIdx.x;   // 0..32767
    const int k = i >> 6;
    const int b = i & 63;
    g_ht[1][i] = h0[(size_t)b * HH + k];
    if (i < NBLK) g_flags[i * 32] = 0;              // reset barrier flags per layer
}

// ---------------- input GEMM (tensor cores, tf32) --------------------------------
// C = A(M,512) * W(512,512) + bias ; BM=128, BN=128, BK=32, 256 thr (8 warps),
// warp tile 64x32 (m16n8k8 x 4m x 4n). blockIdx.z = gate.
// GPITCH = 136 (== 8 mod 32): conflict-free fragment gathers.
#define GPITCH 136
#define GEMM_SMEM_FLOATS (2 * 32 * GPITCH * 2)

__global__ __launch_bounds__(256) void gemm_xw_mma(const float* __restrict__ A,
                                                   const float* __restrict__ W0,
                                                   const float* __restrict__ W1,
                                                   const float* __restrict__ W2,
                                                   const float* __restrict__ bias0,
                                                   const float* __restrict__ bias1,
                                                   const float* __restrict__ bias2) {
    extern __shared__ float gsm[];
    float* Asm = gsm;                         // [2][32][GPITCH] (k-major: [k][m])
    float* Bsm = gsm + 2 * 32 * GPITCH;       // [2][32][GPITCH] ([k][n])
#define AS(b, k, m) Asm[((b) * 32 + (k)) * GPITCH + (m)]
#define BS(b, k, n) Bsm[((b) * 32 + (k)) * GPITCH + (n)]

    const int gate = blockIdx.z;
    const float* W    = (gate == 0) ? W0 : ((gate == 1) ? W1 : W2);
    const float* bias = (gate == 0) ? bias0 : ((gate == 1) ? bias1 : bias2);

    const int bm = blockIdx.x * 128;
    const int bn = blockIdx.y * 128;
    const int tid = threadIdx.x;
    const int lane = tid & 31;
    const int wid = tid >> 5;
    const int warp_m = wid >> 2;              // 0..1
    const int warp_n = wid & 3;               // 0..3

    const int arow = tid >> 1;
    const int ahalf = (tid & 1) << 4;
    const int wk0 = tid >> 5;
    const int wn4 = (tid & 31) << 2;

    float acc[4][4][4];
#pragma unroll
    for (int mt = 0; mt < 4; mt++)
#pragma unroll
        for (int nt = 0; nt < 4; nt++)
#pragma unroll
            for (int i = 0; i < 4; i++) acc[mt][nt][i] = 0.f;

    // preload tile 0
#pragma unroll
    for (int q = 0; q < 4; q++) {
        float4 v = *(const float4*)(A + (size_t)(bm + arow) * HH + ahalf + q * 4);
        AS(0, ahalf + q * 4 + 0, arow) = tf32r(v.x);
        AS(0, ahalf + q * 4 + 1, arow) = tf32r(v.y);
        AS(0, ahalf + q * 4 + 2, arow) = tf32r(v.z);
        AS(0, ahalf + q * 4 + 3, arow) = tf32r(v.w);
    }
#pragma unroll
    for (int s = 0; s < 4; s++) {
        float4 v = *(const float4*)(W + (size_t)(wk0 + s * 8) * HH + bn + wn4);
        v.x = tf32r(v.x); v.y = tf32r(v.y); v.z = tf32r(v.z); v.w = tf32r(v.w);
        *(float4*)&BS(0, wk0 + s * 8, wn4) = v;
    }
    __syncthreads();

    const int r = lane >> 2;
    const int cq = lane & 3;
    const int mrow = warp_m * 64 + r;
    const int nbase = warp_n * 32 + r;

    for (int kt = 0; kt < HH; kt += 32) {
        const int buf = (kt >> 5) & 1;
        const bool more = (kt + 32) < HH;
        float4 pa[4], pw[4];
        if (more) {
#pragma unroll
            for (int q = 0; q < 4; q++)
                pa[q] = *(const float4*)(A + (size_t)(bm + arow) * HH + kt + 32 + ahalf + q * 4);
#pragma unroll
            for (int s = 0; s < 4; s++)
                pw[s] = *(const float4*)(W + (size_t)(kt + 32 + wk0 + s * 8) * HH + bn + wn4);
        }

#pragma unroll
        for (int ks = 0; ks < 4; ks++) {
            const int kk = ks * 8;
            uint32_t af[4][4];
#pragma unroll
            for (int mt = 0; mt < 4; mt++) {
                af[mt][0] = __float_as_uint(AS(buf, kk + cq,     mrow + mt * 16));
                af[mt][1] = __float_as_uint(AS(buf, kk + cq,     mrow + mt * 16 + 8));
                af[mt][2] = __float_as_uint(AS(buf, kk + cq + 4, mrow + mt * 16));
                af[mt][3] = __float_as_uint(AS(buf, kk + cq + 4, mrow + mt * 16 + 8));
            }
            uint32_t bf[4][2];
#pragma unroll
            for (int nt = 0; nt < 4; nt++) {
                bf[nt][0] = __float_as_uint(BS(buf, kk + cq,     nbase + nt * 8));
                bf[nt][1] = __float_as_uint(BS(buf, kk + cq + 4, nbase + nt * 8));
            }
#pragma unroll
            for (int mt = 0; mt < 4; mt++)
#pragma unroll
                for (int nt = 0; nt < 4; nt++)
                    mma_tf32(acc[mt][nt], af[mt], bf[nt]);
        }

        if (more) {
            const int nb = buf ^ 1;
#pragma unroll
            for (int q = 0; q < 4; q++) {
                AS(nb, ahalf + q * 4 + 0, arow) = tf32r(pa[q].x);
                AS(nb, ahalf + q * 4 + 1, arow) = tf32r(pa[q].y);
                AS(nb, ahalf + q * 4 + 2, arow) = tf32r(pa[q].z);
                AS(nb, ahalf + q * 4 + 3, arow) = tf32r(pa[q].w);
            }
#pragma unroll
            for (int s = 0; s < 4; s++) {
                float4 v = pw[s];
                v.x = tf32r(v.x); v.y = tf32r(v.y); v.z = tf32r(v.z); v.w = tf32r(v.w);
                *(float4*)&BS(nb, wk0 + s * 8, wn4) = v;
            }
        }
        __syncthreads();
    }

    // epilogue
    float* C = g_gx[0] + (size_t)gate * ((size_t)TT * BB * HH);
    const int m0 = bm + warp_m * 64 + r;
    const int n0 = bn + warp_n * 32 + 2 * cq;
#pragma unroll
    for (int nt = 0; nt < 4; nt++) {
        const int col = n0 + nt * 8;
        const float b0 = bias[col];
        const float b1 = bias[col + 1];
#pragma unroll
        for (int mt = 0; mt < 4; mt++) {
            const int row0 = m0 + mt * 16;
            float2 v0 = make_float2(acc[mt][nt][0] + b0, acc[mt][nt][1] + b1);
            float2 v1 = make_float2(acc[mt][nt][2] + b0, acc[mt][nt][3] + b1);
            *(float2*)&C[(size_t)row0 * HH + col] = v0;
            *(float2*)&C[(size_t)(row0 + 8) * HH + col] = v1;
        }
    }
#undef AS
#undef BS
}

// ---------------- flag-based grid barrier ----------------------------------------
__device__ __forceinline__ void grid_sync_flags(int target) {
    __syncthreads();
    if (threadIdx.x == 0) {
        asm volatile("st.global.release.gpu.u32 [%0], %1;"
                     :: "l"(&g_flags[blockIdx.x * 32]), "r"((unsigned)target)
                     : "memory");
    }
    if (threadIdx.x < NBLK) {
        unsigned v;
        do {
            asm volatile("ld.global.acquire.gpu.u32 %0, [%1];"
                         : "=r"(v) : "l"(&g_flags[threadIdx.x * 32]) : "memory");
        } while (v < (unsigned)target);
    }
    __syncthreads();
}

// ---------------- persistent recurrence ------------------------------------------
// 128 CTAs x 256 threads. CTA owns 4 hidden columns (3 gates each).
// h is NEVER staged in smem: each lane LDGs exactly the float4s it consumes
// (k-major layout makes them lane-aligned), double-buffered in 8-k chunks.
// Smem holds only weight columns + the cross-warp reduce buffer.
#define WSM_PITCH 16
#define SMEM_FLOATS (HH * WSM_PITCH + 16 * 192 * 2)

__global__ __launch_bounds__(256) void gru_recurrence(
    const float* __restrict__ whr, const float* __restrict__ whz,
    const float* __restrict__ whn,
    const float* __restrict__ bhr, const float* __restrict__ bhz,
    const float* __restrict__ bhn,
    float* __restrict__ seq,          // [T,B,H]
    float* __restrict__ finals)       // [B,H]
{
    extern __shared__ float sm[];
    float* wsm = sm;                               // [512][16] (12 used: g*4+j)
    ull*   red = (ull*)(sm + HH * WSM_PITCH);      // [16][192]

    const int tid = threadIdx.x;
    const int w   = tid >> 5;                 // warp = 64-k slice
    const int lane = tid & 31;
    const int btile = lane >> 1;              // 0..15 -> 4 batches
    const int ct = lane & 1;                  // col pair 2*ct, 2*ct+1
    const int jbase = blockIdx.x * 4;

    // activation-phase identity
    const int ab = tid >> 2;                  // batch
    const int aj = tid & 3;                   // local col
    const int jglob = jbase + aj;
    const int act = aj >> 1;
    const int ahalf = aj & 1;

    // load weight columns (once): wsm[k][g*4+j] = W_g[k][jbase+j]
    for (int i = tid; i < HH * 12; i += 256) {
        const int k = i / 12;
        const int rr = i - k * 12;
        const int g = rr >> 2;
        const int j = rr & 3;
        const float* src = (g == 0) ? whr : ((g == 1) ? whz : whn);
        wsm[k * WSM_PITCH + rr] = src[(size_t)k * HH + jbase + j];
    }
    const float bh_r = bhr[jglob];
    const float bh_z = bhz[jglob];
    const float bh_n = bhn[jglob];
    __syncthreads();

    const float* wbase = wsm + ct * 2;
    // lane's h source: f4 index = k*16 + btile, k = w*64 + c*8 + kk
    const int lbase = w * 1024 + btile;       // float4 index at k = w*64

    for (int t = 0; t < TT; t++) {
        const float4* src4 = (const float4*)g_ht[(t - 1) & 1];

        // prefetch gate-x and h_prev element (hidden under dot)
        const int gi = (t * BB + ab) * HH + jglob;
        const float gxr = __ldcs(&g_gx[0][gi]);
        const float gxz = __ldcs(&g_gx[1][gi]);
        const float gxn = __ldcs(&g_gx[2][gi]);
        const float hp  = __ldcg(&g_ht[(t - 1) & 1][jglob * BB + ab]);

        ull a0r = 0, a1r = 0, a2r = 0, a3r = 0;
        ull a0z = 0, a1z = 0, a2z = 0, a3z = 0;
        ull a0n = 0, a1n = 0, a2n = 0, a3n = 0;

        float4 pf[2][8];
        // preload chunk 0 (8 k)
#pragma unroll
        for (int i = 0; i < 8; i++)
            pf[0][i] = __ldcg(&src4[lbase + i * 16]);

#pragma unroll
        for (int c = 0; c < 8; c++) {
            if (c < 7) {
#pragma unroll
                for (int i = 0; i < 8; i++)
                    pf[(c + 1) & 1][i] =
                        __ldcg(&src4[lbase + (c + 1) * 128 + i * 16]);
            }
#pragma unroll
            for (int kk = 0; kk < 8; kk++) {
                const int k = (w << 6) + (c << 3) + kk;
                float4 h4 = pf[c & 1][kk];
                ull wr = *(const ull*)(wbase + k * WSM_PITCH + 0);
                ull wz = *(const ull*)(wbase + k * WSM_PITCH + 4);
                ull wn = *(const ull*)(wbase + k * WSM_PITCH + 8);
                ull h0p = pk2(h4.x), h1p = pk2(h4.y), h2p = pk2(h4.z), h3p = pk2(h4.w);
                fma2(a0r, h0p, wr); fma2(a1r, h1p, wr); fma2(a2r, h2p, wr); fma2(a3r, h3p, wr);
                fma2(a0z, h0p, wz); fma2(a1z, h1p, wz); fma2(a2z, h2p, wz); fma2(a3z, h3p, wz);
                fma2(a0n, h0p, wn); fma2(a1n, h1p, wn); fma2(a2n, h2p, wn); fma2(a3n, h3p, wn);
            }
        }

        // store partials: red[w*2+ct][g*64 + b]
        {
            ull* rb = red + (size_t)(w * 2 + ct) * 192;
            const int b0 = btile * 4;
            rb[0 * 64 + b0 + 0] = a0r; rb[0 * 64 + b0 + 1] = a1r;
            rb[0 * 64 + b0 + 2] = a2r; rb[0 * 64 + b0 + 3] = a3r;
            rb[1 * 64 + b0 + 0] = a0z; rb[1 * 64 + b0 + 1] = a1z;
            rb[1 * 64 + b0 + 2] = a2z; rb[1 * 64 + b0 + 3] = a3z;
            rb[2 * 64 + b0 + 0] = a0n; rb[2 * 64 + b0 + 1] = a1n;
            rb[2 * 64 + b0 + 2] = a2n; rb[2 * 64 + b0 + 3] = a3n;
        }
        __syncthreads();

        // ---- reduce over 8 warps + activation (thread = (ab, aj)) ----
        float ar = bh_r, az = bh_z, an = bh_n;
        const float* rf = (const float*)red;
#pragma unroll
        for (int ww = 0; ww < 8; ww++) {
            const size_t base = ((size_t)(ww * 2 + act) * 192) * 2 + ahalf;
            ar += rf[base + (0 * 64 + ab) * 2];
            az += rf[base + (1 * 64 + ab) * 2];
            an += rf[base + (2 * 64 + ab) * 2];
        }

        const float rg = 1.f / (1.f + expf(-(gxr + ar)));
        const float zg = 1.f / (1.f + expf(-(gxz + az)));
        const float ng = tanhf(gxn + rg * an);
        const float hn_ = (1.f - zg) * ng + zg * hp;

        __stcg(&g_ht[t & 1][jglob * BB + ab], hn_);   // k-major for next step
        seq[gi] = hn_;
        if (t == TT - 1) finals[(size_t)ab * HH + jglob] = hn_;

        grid_sync_flags(t + 1);
    }
}

// -------------------------------- launch -----------------------------------------
extern "C" void kernel_launch(void* const* d_in, const int* in_sizes, int n_in,
                              void* d_out, int out_size) {
    const float* x    = (const float*)d_in[0];
    const float* init = (const float*)d_in[1];
    const float* w_ir = (const float*)d_in[2];
    const float* w_hr = (const float*)d_in[3];
    const float* w_iz = (const float*)d_in[4];
    const float* w_hz = (const float*)d_in[5];
    const float* w_in = (const float*)d_in[6];
    const float* w_hn = (const float*)d_in[7];
    const float* b_ir = (const float*)d_in[8];
    const float* b_hr = (const float*)d_in[9];
    const float* b_iz = (const float*)d_in[10];
    const float* b_hz = (const float*)d_in[11];
    const float* b_in = (const float*)d_in[12];
    const float* b_hn = (const float*)d_in[13];

    float* out    = (float*)d_out;
    float* seq    = out;                          // [T,B,H]
    float* finals = out + (size_t)TT * BB * HH;   // [L,B,H]

    const size_t rec_smem = (size_t)SMEM_FLOATS * sizeof(float);
    cudaFuncSetAttribute(gru_recurrence,
                         cudaFuncAttributeMaxDynamicSharedMemorySize,
                         (int)rec_smem);
    const size_t gemm_smem = (size_t)GEMM_SMEM_FLOATS * sizeof(float);
    cudaFuncSetAttribute(gemm_xw_mma,
                         cudaFuncAttributeMaxDynamicSharedMemorySize,
                         (int)gemm_smem);

    dim3 ggrid(TT * BB / 128, HH / 128, 3);       // 256 x 4 x 3

    for (int l = 0; l < LL; l++) {
        const float* A = (l == 0) ? x : seq;
        const size_t wo = (size_t)l * HH * HH;
        const size_t bo = (size_t)l * HH;

        gemm_xw_mma<<<ggrid, 256, gemm_smem>>>(A,
                                               w_ir + wo, w_iz + wo, w_in + wo,
                                               b_ir + bo, b_iz + bo, b_in + bo);

        transpose_h0<<<HH * BB / 256, 256>>>(init + (size_t)l * BB * HH);

        gru_recurrence<<<NBLK, 256, rec_smem>>>(
            w_hr + wo, w_hz + wo, w_hn + wo,
            b_hr + bo, b_hz + bo, b_hn + bo,
            seq,
            finals + (size_t)l * BB * HH);
    }
}

// round 9
// speedup vs baseline: 1.7061x; 1.7061x over previous
#include <cuda_runtime.h>
#include <cuda_bf16.h>
#include <math.h>
#include <stdint.h>

#define TT   512
#define BB   64
#define HH   512
#define LL   2
#define NBLK 128          // recurrence grid (1 CTA/SM, all co-resident)

typedef unsigned long long ull;

// ---------------- scratch (__device__ globals; allocation-free) ----------------
__device__ float g_gx[3][TT * BB * HH];     // gate-x planes (r,z,n) for current layer
__device__ float g_ht[2][HH * BB];          // double-buffered hidden state, k-major [k][b]
__device__ unsigned int g_flags[NBLK * 32]; // per-CTA barrier flags, 128B stride

// ---------------- packed fp32x2 helpers (Blackwell) -----------------------------
__device__ __forceinline__ ull pk2(float x) {
    ull r; asm("mov.b64 %0, {%1, %1};" : "=l"(r) : "f"(x)); return r;
}
__device__ __forceinline__ void fma2(ull& acc, ull a, ull b) {
    asm("fma.rn.f32x2 %0, %1, %2, %0;" : "+l"(acc) : "l"(a), "l"(b));
}

// tf32 round-to-nearest of an fp32 (bits usable by mma.tf32)
__device__ __forceinline__ float tf32r(float x) {
    uint32_t y;
    asm("cvt.rna.tf32.f32 %0, %1;" : "=r"(y) : "f"(x));
    return __uint_as_float(y);
}

__device__ __forceinline__ void mma_tf32(float c[4], const uint32_t a[4],
                                         const uint32_t b[2]) {
    asm volatile(
        "mma.sync.aligned.m16n8k8.row.col.f32.tf32.tf32.f32 "
        "{%0,%1,%2,%3}, {%4,%5,%6,%7}, {%8,%9}, {%0,%1,%2,%3};"
        : "+f"(c[0]), "+f"(c[1]), "+f"(c[2]), "+f"(c[3])
        : "r"(a[0]), "r"(a[1]), "r"(a[2]), "r"(a[3]), "r"(b[0]), "r"(b[1]));
}

// cp.async 16B (L2-cached) + group control
__device__ __forceinline__ void cpa16(uint32_t smem, const void* g) {
    asm volatile("cp.async.cg.shared.global [%0], [%1], 16;"
                 :: "r"(smem), "l"(g) : "memory");
}
#define CP_COMMIT()  asm volatile("cp.async.commit_group;" ::: "memory")
#define CP_WAIT_1()  asm volatile("cp.async.wait_group 1;" ::: "memory")
#define CP_WAIT_0()  asm volatile("cp.async.wait_group 0;" ::: "memory")

// ---------------- h0 transpose + barrier-flag reset ------------------------------
__global__ __launch_bounds__(256) void transpose_h0(const float* __restrict__ h0) {
    const int i = blockIdx.x * 256 + threadIdx.x;   // 0..32767
    const int k = i >> 6;
    const int b = i & 63;
    g_ht[1][i] = h0[(size_t)b * HH + k];
    if (i < NBLK) g_flags[i * 32] = 0;              // reset barrier flags per layer
}

// ---------------- input GEMM (tensor cores, tf32) --------------------------------
// C = A(M,512) * W(512,512) + bias ; BM=128, BN=128, BK=32, 256 thr (8 warps),
// warp tile 64x32 (m16n8k8 x 4m x 4n). blockIdx.z = gate.
// GPITCH = 136 (== 8 mod 32): conflict-free fragment gathers.
#define GPITCH 136
#define GEMM_SMEM_FLOATS (2 * 32 * GPITCH * 2)

__global__ __launch_bounds__(256) void gemm_xw_mma(const float* __restrict__ A,
                                                   const float* __restrict__ W0,
                                                   const float* __restrict__ W1,
                                                   const float* __restrict__ W2,
                                                   const float* __restrict__ bias0,
                                                   const float* __restrict__ bias1,
                                                   const float* __restrict__ bias2) {
    extern __shared__ float gsm[];
    float* Asm = gsm;                         // [2][32][GPITCH] (k-major: [k][m])
    float* Bsm = gsm + 2 * 32 * GPITCH;       // [2][32][GPITCH] ([k][n])
#define AS(b, k, m) Asm[((b) * 32 + (k)) * GPITCH + (m)]
#define BS(b, k, n) Bsm[((b) * 32 + (k)) * GPITCH + (n)]

    const int gate = blockIdx.z;
    const float* W    = (gate == 0) ? W0 : ((gate == 1) ? W1 : W2);
    const float* bias = (gate == 0) ? bias0 : ((gate == 1) ? bias1 : bias2);

    const int bm = blockIdx.x * 128;
    const int bn = blockIdx.y * 128;
    const int tid = threadIdx.x;
    const int lane = tid & 31;
    const int wid = tid >> 5;
    const int warp_m = wid >> 2;              // 0..1
    const int warp_n = wid & 3;               // 0..3

    const int arow = tid >> 1;
    const int ahalf = (tid & 1) << 4;
    const int wk0 = tid >> 5;
    const int wn4 = (tid & 31) << 2;

    float acc[4][4][4];
#pragma unroll
    for (int mt = 0; mt < 4; mt++)
#pragma unroll
        for (int nt = 0; nt < 4; nt++)
#pragma unroll
            for (int i = 0; i < 4; i++) acc[mt][nt][i] = 0.f;

    // preload tile 0
#pragma unroll
    for (int q = 0; q < 4; q++) {
        float4 v = *(const float4*)(A + (size_t)(bm + arow) * HH + ahalf + q * 4);
        AS(0, ahalf + q * 4 + 0, arow) = tf32r(v.x);
        AS(0, ahalf + q * 4 + 1, arow) = tf32r(v.y);
        AS(0, ahalf + q * 4 + 2, arow) = tf32r(v.z);
        AS(0, ahalf + q * 4 + 3, arow) = tf32r(v.w);
    }
#pragma unroll
    for (int s = 0; s < 4; s++) {
        float4 v = *(const float4*)(W + (size_t)(wk0 + s * 8) * HH + bn + wn4);
        v.x = tf32r(v.x); v.y = tf32r(v.y); v.z = tf32r(v.z); v.w = tf32r(v.w);
        *(float4*)&BS(0, wk0 + s * 8, wn4) = v;
    }
    __syncthreads();

    const int r = lane >> 2;
    const int cq = lane & 3;
    const int mrow = warp_m * 64 + r;
    const int nbase = warp_n * 32 + r;

    for (int kt = 0; kt < HH; kt += 32) {
        const int buf = (kt >> 5) & 1;
        const bool more = (kt + 32) < HH;
        float4 pa[4], pw[4];
        if (more) {
#pragma unroll
            for (int q = 0; q < 4; q++)
                pa[q] = *(const float4*)(A + (size_t)(bm + arow) * HH + kt + 32 + ahalf + q * 4);
#pragma unroll
            for (int s = 0; s < 4; s++)
                pw[s] = *(const float4*)(W + (size_t)(kt + 32 + wk0 + s * 8) * HH + bn + wn4);
        }

#pragma unroll
        for (int ks = 0; ks < 4; ks++) {
            const int kk = ks * 8;
            uint32_t af[4][4];
#pragma unroll
            for (int mt = 0; mt < 4; mt++) {
                af[mt][0] = __float_as_uint(AS(buf, kk + cq,     mrow + mt * 16));
                af[mt][1] = __float_as_uint(AS(buf, kk + cq,     mrow + mt * 16 + 8));
                af[mt][2] = __float_as_uint(AS(buf, kk + cq + 4, mrow + mt * 16));
                af[mt][3] = __float_as_uint(AS(buf, kk + cq + 4, mrow + mt * 16 + 8));
            }
            uint32_t bf[4][2];
#pragma unroll
            for (int nt = 0; nt < 4; nt++) {
                bf[nt][0] = __float_as_uint(BS(buf, kk + cq,     nbase + nt * 8));
                bf[nt][1] = __float_as_uint(BS(buf, kk + cq + 4, nbase + nt * 8));
            }
#pragma unroll
            for (int mt = 0; mt < 4; mt++)
#pragma unroll
                for (int nt = 0; nt < 4; nt++)
                    mma_tf32(acc[mt][nt], af[mt], bf[nt]);
        }

        if (more) {
            const int nb = buf ^ 1;
#pragma unroll
            for (int q = 0; q < 4; q++) {
                AS(nb, ahalf + q * 4 + 0, arow) = tf32r(pa[q].x);
                AS(nb, ahalf + q * 4 + 1, arow) = tf32r(pa[q].y);
                AS(nb, ahalf + q * 4 + 2, arow) = tf32r(pa[q].z);
                AS(nb, ahalf + q * 4 + 3, arow) = tf32r(pa[q].w);
            }
#pragma unroll
            for (int s = 0; s < 4; s++) {
                float4 v = pw[s];
                v.x = tf32r(v.x); v.y = tf32r(v.y); v.z = tf32r(v.z); v.w = tf32r(v.w);
                *(float4*)&BS(nb, wk0 + s * 8, wn4) = v;
            }
        }
        __syncthreads();
    }

    // epilogue
    float* C = g_gx[0] + (size_t)gate * ((size_t)TT * BB * HH);
    const int m0 = bm + warp_m * 64 + r;
    const int n0 = bn + warp_n * 32 + 2 * cq;
#pragma unroll
    for (int nt = 0; nt < 4; nt++) {
        const int col = n0 + nt * 8;
        const float b0 = bias[col];
        const float b1 = bias[col + 1];
#pragma unroll
        for (int mt = 0; mt < 4; mt++) {
            const int row0 = m0 + mt * 16;
            float2 v0 = make_float2(acc[mt][nt][0] + b0, acc[mt][nt][1] + b1);
            float2 v1 = make_float2(acc[mt][nt][2] + b0, acc[mt][nt][3] + b1);
            *(float2*)&C[(size_t)row0 * HH + col] = v0;
            *(float2*)&C[(size_t)(row0 + 8) * HH + col] = v1;
        }
    }
#undef AS
#undef BS
}

// ---------------- flag-based grid barrier ----------------------------------------
__device__ __forceinline__ void grid_sync_flags(int target) {
    __syncthreads();
    if (threadIdx.x == 0) {
        asm volatile("st.global.release.gpu.u32 [%0], %1;"
                     :: "l"(&g_flags[blockIdx.x * 32]), "r"((unsigned)target)
                     : "memory");
    }
    if (threadIdx.x < NBLK) {
        unsigned v;
        do {
            asm volatile("ld.global.acquire.gpu.u32 %0, [%1];"
                         : "=r"(v) : "l"(&g_flags[threadIdx.x * 32]) : "memory");
        } while (v < (unsigned)target);
    }
    __syncthreads();
}

// ---------------- persistent recurrence ------------------------------------------
// 128 CTAs x 256 threads. CTA owns 4 hidden columns (3 gates each).
// Dot: warp = 64-k slice, 4 x 16-k chunks staged into smem via cp.async,
// pipelined 2 chunks deep. lane: btile = lane>>1 (4 batches), ct = lane&1.
// Weights packed [k][ct][wr0,wr1,wz0,wz1,wn0,wn1,(pad x2)] -> 2 LDS per k.
#define WSM_PITCH 16
#define SMEM_FLOATS (HH * BB + HH * WSM_PITCH + 16 * 192 * 2)

__global__ __launch_bounds__(256) void gru_recurrence(
    const float* __restrict__ whr, const float* __restrict__ whz,
    const float* __restrict__ whn,
    const float* __restrict__ bhr, const float* __restrict__ bhz,
    const float* __restrict__ bhn,
    float* __restrict__ seq,          // [T,B,H]
    float* __restrict__ finals)       // [B,H]
{
    extern __shared__ float sm[];
    float* ht  = sm;                          // [512][64] h (k-major)
    float* wsm = sm + HH * BB;                // [512][16] packed
    ull*   red = (ull*)(sm + HH * BB + HH * WSM_PITCH);  // [16][192]

    const int tid = threadIdx.x;
    const int w   = tid >> 5;                 // warp = 64-k slice
    const int lane = tid & 31;
    const int btile = lane >> 1;              // 0..15 -> 4 batches
    const int ct = lane & 1;                  // col pair 2*ct, 2*ct+1
    const int jbase = blockIdx.x * 4;

    // activation-phase identity
    const int ab = tid >> 2;                  // batch
    const int aj = tid & 3;                   // local col
    const int jglob = jbase + aj;
    const int act = aj >> 1;
    const int ahalf = aj & 1;

    // load weight columns (once), packed: wsm[k*16 + ct*8 + g*2 + e]
    for (int i = tid; i < HH * 12; i += 256) {
        const int k = i / 12;
        const int rr = i - k * 12;
        const int g = rr >> 2;
        const int j = rr & 3;
        const int ctl = j >> 1;
        const int e  = j & 1;
        const float* src = (g == 0) ? whr : ((g == 1) ? whz : whn);
        wsm[k * WSM_PITCH + ctl * 8 + g * 2 + e] = src[(size_t)k * HH + jbase + j];
    }
    const float bh_r = bhr[jglob];
    const float bh_z = bhz[jglob];
    const float bh_n = bhn[jglob];
    __syncthreads();

    const float* hbase = ht + btile * 4;
    const float* wbase = wsm + ct * 8;
    // warp's slice: float4 index range [slice_f4, slice_f4+1024), chunks of 256
    const int slice_f4 = w * 1024;
    const uint32_t ht_u32 = (uint32_t)__cvta_generic_to_shared(ht);

    for (int t = 0; t < TT; t++) {
        // prefetch gate-x (hidden under dot)
        const int gi = (t * BB + ab) * HH + jglob;
        const float gxr = __ldcs(&g_gx[0][gi]);
        const float gxz = __ldcs(&g_gx[1][gi]);
        const float gxn = __ldcs(&g_gx[2][gi]);

        const float4* src4 = (const float4*)g_ht[(t - 1) & 1];

        ull a0r = 0, a1r = 0, a2r = 0, a3r = 0;
        ull a0z = 0, a1z = 0, a2z = 0, a3z = 0;
        ull a0n = 0, a1n = 0, a2n = 0, a3n = 0;

        // issue chunks 0 and 1 (cp.async: gmem -> smem, no registers)
#pragma unroll
        for (int i = 0; i < 8; i++)
            cpa16(ht_u32 + (uint32_t)(slice_f4 + i * 32 + lane) * 16,
                  src4 + slice_f4 + i * 32 + lane);
        CP_COMMIT();
#pragma unroll
        for (int i = 0; i < 8; i++)
            cpa16(ht_u32 + (uint32_t)(slice_f4 + 256 + i * 32 + lane) * 16,
                  src4 + slice_f4 + 256 + i * 32 + lane);
        CP_COMMIT();

#pragma unroll
        for (int c = 0; c < 4; c++) {
            if (c < 3) CP_WAIT_1(); else CP_WAIT_0();
            __syncwarp();

#pragma unroll
            for (int kk = 0; kk < 16; kk++) {
                const int k = (w << 6) + (c << 4) + kk;
                float4 h4 = *(const float4*)(hbase + k * BB);
                ulonglong2 wrz = *(const ulonglong2*)(wbase + k * WSM_PITCH);
                ull wn = *(const ull*)(wbase + k * WSM_PITCH + 4);
                ull wr = wrz.x, wz = wrz.y;
                ull h0p = pk2(h4.x), h1p = pk2(h4.y), h2p = pk2(h4.z), h3p = pk2(h4.w);
                fma2(a0r, h0p, wr); fma2(a1r, h1p, wr); fma2(a2r, h2p, wr); fma2(a3r, h3p, wr);
                fma2(a0z, h0p, wz); fma2(a1z, h1p, wz); fma2(a2z, h2p, wz); fma2(a3z, h3p, wz);
                fma2(a0n, h0p, wn); fma2(a1n, h1p, wn); fma2(a2n, h2p, wn); fma2(a3n, h3p, wn);
            }

            if (c < 2) {
#pragma unroll
                for (int i = 0; i < 8; i++)
                    cpa16(ht_u32 + (uint32_t)(slice_f4 + (c + 2) * 256 + i * 32 + lane) * 16,
                          src4 + slice_f4 + (c + 2) * 256 + i * 32 + lane);
                CP_COMMIT();
            }
        }

        // store partials: red[w*2+ct][g*64 + b]
        {
            ull* rb = red + (size_t)(w * 2 + ct) * 192;
            const int b0 = btile * 4;
            rb[0 * 64 + b0 + 0] = a0r; rb[0 * 64 + b0 + 1] = a1r;
            rb[0 * 64 + b0 + 2] = a2r; rb[0 * 64 + b0 + 3] = a3r;
            rb[1 * 64 + b0 + 0] = a0z; rb[1 * 64 + b0 + 1] = a1z;
            rb[1 * 64 + b0 + 2] = a2z; rb[1 * 64 + b0 + 3] = a3z;
            rb[2 * 64 + b0 + 0] = a0n; rb[2 * 64 + b0 + 1] = a1n;
            rb[2 * 64 + b0 + 2] = a2n; rb[2 * 64 + b0 + 3] = a3n;
        }
        __syncthreads();

        // ---- reduce over 8 warps + activation (thread = (ab, aj)) ----
        float ar = bh_r, az = bh_z, an = bh_n;
        const float* rf = (const float*)red;
#pragma unroll
        for (int ww = 0; ww < 8; ww++) {
            const size_t base = ((size_t)(ww * 2 + act) * 192) * 2 + ahalf;
            ar += rf[base + (0 * 64 + ab) * 2];
            az += rf[base + (1 * 64 + ab) * 2];
            an += rf[base + (2 * 64 + ab) * 2];
        }

        const float rg = 1.f / (1.f + expf(-(gxr + ar)));
        const float zg = 1.f / (1.f + expf(-(gxz + az)));
        const float ng = tanhf(gxn + rg * an);
        const float hp = ht[jglob * BB + ab];
        const float hn_ = (1.f - zg) * ng + zg * hp;

        __stcg(&g_ht[t & 1][jglob * BB + ab], hn_);   // k-major for next step
        seq[gi] = hn_;
        if (t == TT - 1) finals[(size_t)ab * HH + jglob] = hn_;

        grid_sync_flags(t + 1);
    }
}

// -------------------------------- launch -----------------------------------------
extern "C" void kernel_launch(void* const* d_in, const int* in_sizes, int n_in,
                              void* d_out, int out_size) {
    const float* x    = (const float*)d_in[0];
    const float* init = (const float*)d_in[1];
    const float* w_ir = (const float*)d_in[2];
    const float* w_hr = (const float*)d_in[3];
    const float* w_iz = (const float*)d_in[4];
    const float* w_hz = (const float*)d_in[5];
    const float* w_in = (const float*)d_in[6];
    const float* w_hn = (const float*)d_in[7];
    const float* b_ir = (const float*)d_in[8];
    const float* b_hr = (const float*)d_in[9];
    const float* b_iz = (const float*)d_in[10];
    const float* b_hz = (const float*)d_in[11];
    const float* b_in = (const float*)d_in[12];
    const float* b_hn = (const float*)d_in[13];

    float* out    = (float*)d_out;
    float* seq    = out;                          // [T,B,H]
    float* finals = out + (size_t)TT * BB * HH;   // [L,B,H]

    const size_t rec_smem = (size_t)SMEM_FLOATS * sizeof(float);
    cudaFuncSetAttribute(gru_recurrence,
                         cudaFuncAttributeMaxDynamicSharedMemorySize,
                         (int)rec_smem);
    const size_t gemm_smem = (size_t)GEMM_SMEM_FLOATS * sizeof(float);
    cudaFuncSetAttribute(gemm_xw_mma,
                         cudaFuncAttributeMaxDynamicSharedMemorySize,
                         (int)gemm_smem);

    dim3 ggrid(TT * BB / 128, HH / 128, 3);       // 256 x 4 x 3

    for (int l = 0; l < LL; l++) {
        const float* A = (l == 0) ? x : seq;
        const size_t wo = (size_t)l * HH * HH;
        const size_t bo = (size_t)l * HH;

        gemm_xw_mma<<<ggrid, 256, gemm_smem>>>(A,
                                               w_ir + wo, w_iz + wo, w_in + wo,
                                               b_ir + bo, b_iz + bo, b_in + bo);

        transpose_h0<<<HH * BB / 256, 256>>>(init + (size_t)l * BB * HH);

        gru_recurrence<<<NBLK, 256, rec_smem>>>(
            w_hr + wo, w_hz + wo, w_hn + wo,
            b_hr + bo, b_hz + bo, b_hn + bo,
            seq,
            finals + (size_t)l * BB * HH);
    }
}

// round 10
// speedup vs baseline: 1.8056x; 1.0583x over previous
#include <cuda_runtime.h>
#include <cuda_bf16.h>
#include <math.h>
#include <stdint.h>

#define TT   512
#define BB   64
#define HH   512
#define LL   2
#define NBLK 128          // recurrence grid (1 CTA/SM, all co-resident)

typedef unsigned long long ull;

// ---------------- scratch (__device__ globals; allocation-free) ----------------
__device__ float g_gx[3][TT * BB * HH];     // gate-x planes (r,z,n) for current layer
__device__ float g_ht[2][HH * BB];          // double-buffered hidden state, k-major [k][b] (tf32-rounded)
__device__ unsigned int g_flags[NBLK * 32]; // per-CTA barrier flags, 128B stride

// tf32 round-to-nearest of an fp32 (bits usable by mma.tf32)
__device__ __forceinline__ float tf32r(float x) {
    uint32_t y;
    asm("cvt.rna.tf32.f32 %0, %1;" : "=r"(y) : "f"(x));
    return __uint_as_float(y);
}

__device__ __forceinline__ void mma_tf32(float c[4], const uint32_t a[4],
                                         const uint32_t b[2]) {
    asm volatile(
        "mma.sync.aligned.m16n8k8.row.col.f32.tf32.tf32.f32 "
        "{%0,%1,%2,%3}, {%4,%5,%6,%7}, {%8,%9}, {%0,%1,%2,%3};"
        : "+f"(c[0]), "+f"(c[1]), "+f"(c[2]), "+f"(c[3])
        : "r"(a[0]), "r"(a[1]), "r"(a[2]), "r"(a[3]), "r"(b[0]), "r"(b[1]));
}

// cp.async 16B (L2-cached) + group control
__device__ __forceinline__ void cpa16(uint32_t smem, const void* g) {
    asm volatile("cp.async.cg.shared.global [%0], [%1], 16;"
                 :: "r"(smem), "l"(g) : "memory");
}
#define CP_COMMIT()  asm volatile("cp.async.commit_group;" ::: "memory")
#define CP_WAIT_1()  asm volatile("cp.async.wait_group 1;" ::: "memory")
#define CP_WAIT_0()  asm volatile("cp.async.wait_group 0;" ::: "memory")

// ---------------- h0 transpose + barrier-flag reset ------------------------------
__global__ __launch_bounds__(256) void transpose_h0(const float* __restrict__ h0) {
    const int i = blockIdx.x * 256 + threadIdx.x;   // 0..32767
    const int k = i >> 6;
    const int b = i & 63;
    g_ht[1][i] = tf32r(h0[(size_t)b * HH + k]);
    if (i < NBLK) g_flags[i * 32] = 0;              // reset barrier flags per layer
}

// ---------------- input GEMM (tensor cores, tf32) --------------------------------
// C = A(M,512) * W(512,512) + bias ; BM=128, BN=128, BK=32, 256 thr (8 warps),
// warp tile 64x32 (m16n8k8 x 4m x 4n). blockIdx.z = gate.
// GPITCH = 136 (== 8 mod 32): conflict-free fragment gathers.
#define GPITCH 136
#define GEMM_SMEM_FLOATS (2 * 32 * GPITCH * 2)

__global__ __launch_bounds__(256) void gemm_xw_mma(const float* __restrict__ A,
                                                   const float* __restrict__ W0,
                                                   const float* __restrict__ W1,
                                                   const float* __restrict__ W2,
                                                   const float* __restrict__ bias0,
                                                   const float* __restrict__ bias1,
                                                   const float* __restrict__ bias2) {
    extern __shared__ float gsm[];
    float* Asm = gsm;                         // [2][32][GPITCH] (k-major: [k][m])
    float* Bsm = gsm + 2 * 32 * GPITCH;       // [2][32][GPITCH] ([k][n])
#define AS(b, k, m) Asm[((b) * 32 + (k)) * GPITCH + (m)]
#define BS(b, k, n) Bsm[((b) * 32 + (k)) * GPITCH + (n)]

    const int gate = blockIdx.z;
    const float* W    = (gate == 0) ? W0 : ((gate == 1) ? W1 : W2);
    const float* bias = (gate == 0) ? bias0 : ((gate == 1) ? bias1 : bias2);

    const int bm = blockIdx.x * 128;
    const int bn = blockIdx.y * 128;
    const int tid = threadIdx.x;
    const int lane = tid & 31;
    const int wid = tid >> 5;
    const int warp_m = wid >> 2;              // 0..1
    const int warp_n = wid & 3;               // 0..3

    const int arow = tid >> 1;
    const int ahalf = (tid & 1) << 4;
    const int wk0 = tid >> 5;
    const int wn4 = (tid & 31) << 2;

    float acc[4][4][4];
#pragma unroll
    for (int mt = 0; mt < 4; mt++)
#pragma unroll
        for (int nt = 0; nt < 4; nt++)
#pragma unroll
            for (int i = 0; i < 4; i++) acc[mt][nt][i] = 0.f;

    // preload tile 0
#pragma unroll
    for (int q = 0; q < 4; q++) {
        float4 v = *(const float4*)(A + (size_t)(bm + arow) * HH + ahalf + q * 4);
        AS(0, ahalf + q * 4 + 0, arow) = tf32r(v.x);
        AS(0, ahalf + q * 4 + 1, arow) = tf32r(v.y);
        AS(0, ahalf + q * 4 + 2, arow) = tf32r(v.z);
        AS(0, ahalf + q * 4 + 3, arow) = tf32r(v.w);
    }
#pragma unroll
    for (int s = 0; s < 4; s++) {
        float4 v = *(const float4*)(W + (size_t)(wk0 + s * 8) * HH + bn + wn4);
        v.x = tf32r(v.x); v.y = tf32r(v.y); v.z = tf32r(v.z); v.w = tf32r(v.w);
        *(float4*)&BS(0, wk0 + s * 8, wn4) = v;
    }
    __syncthreads();

    const int r = lane >> 2;
    const int cq = lane & 3;
    const int mrow = warp_m * 64 + r;
    const int nbase = warp_n * 32 + r;

    for (int kt = 0; kt < HH; kt += 32) {
        const int buf = (kt >> 5) & 1;
        const bool more = (kt + 32) < HH;
        float4 pa[4], pw[4];
        if (more) {
#pragma unroll
            for (int q = 0; q < 4; q++)
                pa[q] = *(const float4*)(A + (size_t)(bm + arow) * HH + kt + 32 + ahalf + q * 4);
#pragma unroll
            for (int s = 0; s < 4; s++)
                pw[s] = *(const float4*)(W + (size_t)(kt + 32 + wk0 + s * 8) * HH + bn + wn4);
        }

#pragma unroll
        for (int ks = 0; ks < 4; ks++) {
            const int kk = ks * 8;
            uint32_t af[4][4];
#pragma unroll
            for (int mt = 0; mt < 4; mt++) {
                af[mt][0] = __float_as_uint(AS(buf, kk + cq,     mrow + mt * 16));
                af[mt][1] = __float_as_uint(AS(buf, kk + cq,     mrow + mt * 16 + 8));
                af[mt][2] = __float_as_uint(AS(buf, kk + cq + 4, mrow + mt * 16));
                af[mt][3] = __float_as_uint(AS(buf, kk + cq + 4, mrow + mt * 16 + 8));
            }
            uint32_t bf[4][2];
#pragma unroll
            for (int nt = 0; nt < 4; nt++) {
                bf[nt][0] = __float_as_uint(BS(buf, kk + cq,     nbase + nt * 8));
                bf[nt][1] = __float_as_uint(BS(buf, kk + cq + 4, nbase + nt * 8));
            }
#pragma unroll
            for (int mt = 0; mt < 4; mt++)
#pragma unroll
                for (int nt = 0; nt < 4; nt++)
                    mma_tf32(acc[mt][nt], af[mt], bf[nt]);
        }

        if (more) {
            const int nb = buf ^ 1;
#pragma unroll
            for (int q = 0; q < 4; q++) {
                AS(nb, ahalf + q * 4 + 0, arow) = tf32r(pa[q].x);
                AS(nb, ahalf + q * 4 + 1, arow) = tf32r(pa[q].y);
                AS(nb, ahalf + q * 4 + 2, arow) = tf32r(pa[q].z);
                AS(nb, ahalf + q * 4 + 3, arow) = tf32r(pa[q].w);
            }
#pragma unroll
            for (int s = 0; s < 4; s++) {
                float4 v = pw[s];
                v.x = tf32r(v.x); v.y = tf32r(v.y); v.z = tf32r(v.z); v.w = tf32r(v.w);
                *(float4*)&BS(nb, wk0 + s * 8, wn4) = v;
            }
        }
        __syncthreads();
    }

    // epilogue
    float* C = g_gx[0] + (size_t)gate * ((size_t)TT * BB * HH);
    const int m0 = bm + warp_m * 64 + r;
    const int n0 = bn + warp_n * 32 + 2 * cq;
#pragma unroll
    for (int nt = 0; nt < 4; nt++) {
        const int col = n0 + nt * 8;
        const float b0 = bias[col];
        const float b1 = bias[col + 1];
#pragma unroll
        for (int mt = 0; mt < 4; mt++) {
            const int row0 = m0 + mt * 16;
            float2 v0 = make_float2(acc[mt][nt][0] + b0, acc[mt][nt][1] + b1);
            float2 v1 = make_float2(acc[mt][nt][2] + b0, acc[mt][nt][3] + b1);
            *(float2*)&C[(size_t)row0 * HH + col] = v0;
            *(float2*)&C[(size_t)(row0 + 8) * HH + col] = v1;
        }
    }
#undef AS
#undef BS
}

// ---------------- flag-based grid barrier ----------------------------------------
__device__ __forceinline__ void grid_sync_flags(int target) {
    __syncthreads();
    if (threadIdx.x == 0) {
        asm volatile("st.global.release.gpu.u32 [%0], %1;"
                     :: "l"(&g_flags[blockIdx.x * 32]), "r"((unsigned)target)
                     : "memory");
    }
    if (threadIdx.x < NBLK) {
        unsigned v;
        do {
            asm volatile("ld.global.acquire.gpu.u32 %0, [%1];"
                         : "=r"(v) : "l"(&g_flags[threadIdx.x * 32]) : "memory");
        } while (v < (unsigned)target);
    }
    __syncthreads();
}

// ---------------- persistent recurrence (tf32 tensor-core dot) -------------------
// 128 CTAs x 256 threads. CTA owns 4 hidden columns (3 gates x 4 cols = N=12,
// padded to 16). Warp = 64-k slice: 8 x m16n8k8 k-steps, 4 m-tiles (M=64 batch),
// 2 n-tiles. B (weight) fragments live in registers for all 512 steps.
// h staged to smem (pitch 72: conflict-free A gathers) via cp.async, 16-k chunks,
// 2-deep pipeline. h is stored tf32-pre-rounded, so the loop has no converts.
#define HTP  72
#define REDP 18
#define SMEM_FLOATS (HH * HTP + 8 * 64 * REDP)

__global__ __launch_bounds__(256) void gru_recurrence(
    const float* __restrict__ whr, const float* __restrict__ whz,
    const float* __restrict__ whn,
    const float* __restrict__ bhr, const float* __restrict__ bhz,
    const float* __restrict__ bhn,
    float* __restrict__ seq,          // [T,B,H]
    float* __restrict__ finals)       // [B,H]
{
    extern __shared__ float sm[];
    float* ht  = sm;                          // [512][HTP] h (k-major, tf32 bits)
    float* red = sm + HH * HTP;               // [8][64][REDP] partials

    const int tid = threadIdx.x;
    const int w   = tid >> 5;                 // warp = 64-k slice
    const int lane = tid & 31;
    const int r  = lane >> 2;                 // fragment row group
    const int cq = lane & 3;                  // fragment col group
    const int jbase = blockIdx.x * 4;

    // activation-phase identity
    const int ab = tid >> 2;                  // batch
    const int aj = tid & 3;                   // local col
    const int jglob = jbase + aj;

    // ---- load W fragments (once, resident all 512 steps) ----
    // b0: (k = ks*8 + cq, n = nt*8 + r); b1: k+4.  n = g*4+j (12 real, 4 pad=0)
    uint32_t bw[8][2][2];
#pragma unroll
    for (int ks = 0; ks < 8; ks++)
#pragma unroll
        for (int nt = 0; nt < 2; nt++)
#pragma unroll
            for (int e = 0; e < 2; e++) {
                const int k = (w << 6) + ks * 8 + cq + e * 4;
                const int n = nt * 8 + r;
                float v = 0.f;
                if (n < 12) {
                    const int g = n >> 2;
                    const int j = n & 3;
                    const float* src = (g == 0) ? whr : ((g == 1) ? whz : whn);
                    v = tf32r(src[(size_t)k * HH + jbase + j]);
                }
                bw[ks][nt][e] = __float_as_uint(v);
            }
    const float bh_r = bhr[jglob];
    const float bh_z = bhz[jglob];
    const float bh_n = bhn[jglob];
    __syncthreads();

    const uint32_t ht_u32 = (uint32_t)__cvta_generic_to_shared(ht);

#define ISSUE_CHUNK(cc)                                                          \
    {                                                                            \
        _Pragma("unroll")                                                        \
        for (int i = 0; i < 8; i++) {                                            \
            const int id = i * 32 + lane;                                        \
            const int row = (w << 6) + (cc) * 16 + (id >> 4);                    \
            const int col4 = id & 15;                                            \
            cpa16(ht_u32 + (uint32_t)(row * HTP + col4 * 4) * 4u,                \
                  src4 + row * 16 + col4);                                       \
        }                                                                        \
        CP_COMMIT();                                                             \
    }

    for (int t = 0; t < TT; t++) {
        // prefetch gate-x and h_prev element (hidden under dot)
        const int gi = (t * BB + ab) * HH + jglob;
        const float gxr = __ldcs(&g_gx[0][gi]);
        const float gxz = __ldcs(&g_gx[1][gi]);
        const float gxn = __ldcs(&g_gx[2][gi]);
        const float hp  = __ldcg(&g_ht[(t - 1) & 1][jglob * BB + ab]);

        const float4* src4 = (const float4*)g_ht[(t - 1) & 1];

        float cacc[4][2][4];
#pragma unroll
        for (int mt = 0; mt < 4; mt++)
#pragma unroll
            for (int nt = 0; nt < 2; nt++)
#pragma unroll
                for (int i = 0; i < 4; i++) cacc[mt][nt][i] = 0.f;

        ISSUE_CHUNK(0)
        ISSUE_CHUNK(1)

#pragma unroll
        for (int c = 0; c < 4; c++) {
            if (c < 3) CP_WAIT_1(); else CP_WAIT_0();
            __syncwarp();

#pragma unroll
            for (int ks2 = 0; ks2 < 2; ks2++) {
                const int ks = c * 2 + ks2;
                const int kb = ((w << 3) + ks) * 8;    // global k base of this step
#pragma unroll
                for (int mt = 0; mt < 4; mt++) {
                    uint32_t a[4];
                    const int base = (kb + cq) * HTP + mt * 16 + r;
                    a[0] = __float_as_uint(ht[base]);
                    a[1] = __float_as_uint(ht[base + 8]);
                    a[2] = __float_as_uint(ht[base + 4 * HTP]);
                    a[3] = __float_as_uint(ht[base + 4 * HTP + 8]);
                    mma_tf32(cacc[mt][0], a, bw[ks][0]);
                    mma_tf32(cacc[mt][1], a, bw[ks][1]);
                }
            }
            if (c < 2) ISSUE_CHUNK(c + 2)
        }

        // store partials: red[w][b][n] (pitch REDP, float2 per c-pair)
        {
            float* rb = red + w * (64 * REDP);
#pragma unroll
            for (int mt = 0; mt < 4; mt++)
#pragma unroll
                for (int nt = 0; nt < 2; nt++) {
                    const int n0 = nt * 8 + 2 * cq;
                    const int b0 = mt * 16 + r;
                    *(float2*)&rb[b0 * REDP + n0] =
                        make_float2(cacc[mt][nt][0], cacc[mt][nt][1]);
                    *(float2*)&rb[(b0 + 8) * REDP + n0] =
                        make_float2(cacc[mt][nt][2], cacc[mt][nt][3]);
                }
        }
        __syncthreads();

        // ---- reduce over 8 warps + activation (thread = (ab, aj)) ----
        float ar = bh_r, az = bh_z, an = bh_n;
#pragma unroll
        for (int ww = 0; ww < 8; ww++) {
            const float* rb = red + ww * (64 * REDP) + ab * REDP + aj;
            ar += rb[0];
            az += rb[4];
            an += rb[8];
        }

        const float rg = 1.f / (1.f + expf(-(gxr + ar)));
        const float zg = 1.f / (1.f + expf(-(gxz + az)));
        const float ng = tanhf(gxn + rg * an);
        const float hn_ = (1.f - zg) * ng + zg * hp;

        __stcg(&g_ht[t & 1][jglob * BB + ab], tf32r(hn_));  // tf32 bits for mma
        seq[gi] = hn_;
        if (t == TT - 1) finals[(size_t)ab * HH + jglob] = hn_;

        grid_sync_flags(t + 1);
    }
#undef ISSUE_CHUNK
}

// -------------------------------- launch -----------------------------------------
extern "C" void kernel_launch(void* const* d_in, const int* in_sizes, int n_in,
                              void* d_out, int out_size) {
    const float* x    = (const float*)d_in[0];
    const float* init = (const float*)d_in[1];
    const float* w_ir = (const float*)d_in[2];
    const float* w_hr = (const float*)d_in[3];
    const float* w_iz = (const float*)d_in[4];
    const float* w_hz = (const float*)d_in[5];
    const float* w_in = (const float*)d_in[6];
    const float* w_hn = (const float*)d_in[7];
    const float* b_ir = (const float*)d_in[8];
    const float* b_hr = (const float*)d_in[9];
    const float* b_iz = (const float*)d_in[10];
    const float* b_hz = (const float*)d_in[11];
    const float* b_in = (const float*)d_in[12];
    const float* b_hn = (const float*)d_in[13];

    float* out    = (float*)d_out;
    float* seq    = out;                          // [T,B,H]
    float* finals = out + (size_t)TT * BB * HH;   // [L,B,H]

    const size_t rec_smem = (size_t)SMEM_FLOATS * sizeof(float);
    cudaFuncSetAttribute(gru_recurrence,
                         cudaFuncAttributeMaxDynamicSharedMemorySize,
                         (int)rec_smem);
    const size_t gemm_smem = (size_t)GEMM_SMEM_FLOATS * sizeof(float);
    cudaFuncSetAttribute(gemm_xw_mma,
                         cudaFuncAttributeMaxDynamicSharedMemorySize,
                         (int)gemm_smem);

    dim3 ggrid(TT * BB / 128, HH / 128, 3);       // 256 x 4 x 3

    for (int l = 0; l < LL; l++) {
        const float* A = (l == 0) ? x : seq;
        const size_t wo = (size_t)l * HH * HH;
        const size_t bo = (size_t)l * HH;

        gemm_xw_mma<<<ggrid, 256, gemm_smem>>>(A,
                                               w_ir + wo, w_iz + wo, w_in + wo,
                                               b_ir + bo, b_iz + bo, b_in + bo);

        transpose_h0<<<HH * BB / 256, 256>>>(init + (size_t)l * BB * HH);

        gru_recurrence<<<NBLK, 256, rec_smem>>>(
            w_hr + wo, w_hz + wo, w_hn + wo,
            b_hr + bo, b_hz + bo, b_hn + bo,
            seq,
            finals + (size_t)l * BB * HH);
    }
}